// round 16
// baseline (speedup 1.0000x reference)
#include <cuda_runtime.h>
#include <cuda_fp16.h>
#include <cstdint>
#include <math.h>

#define NB   8
#define NC   1536
#define HWSZ 1024
#define NG   24
#define CPG  64

__device__ __half g_xh[(size_t)NB * NC * HWSZ];   // GN-normalized fp16 tensor

// pack two floats into half2 {lo=a, hi=b}
__device__ __forceinline__ uint32_t packh2(float a, float b) {
    uint32_t r;
    asm("cvt.rn.f16x2.f32 %0, %1, %2;" : "=r"(r) : "f"(b), "f"(a));
    return r;
}

// ---------------------------------------------------------------------------
// Kernel A (fused): per-(b,group) stats + fp16 conversion in one pass.
// ---------------------------------------------------------------------------
__global__ __launch_bounds__(1024)
void gn_fused_kernel(const float* __restrict__ x,
                     const float* __restrict__ w,
                     const float* __restrict__ bs) {
    const int b = blockIdx.x / NG;
    const int g = blockIdx.x % NG;
    const int tid = threadIdx.x;
    const size_t base = ((size_t)b * NC + (size_t)g * CPG) * HWSZ;
    const float4* p4 = (const float4*)(x + base);

    float s0 = 0.f, s1 = 0.f, s2 = 0.f, s3 = 0.f;
    float q0 = 0.f, q1 = 0.f, q2 = 0.f, q3 = 0.f;
    #pragma unroll
    for (int k = 0; k < 4; k++) {
        float4 a = p4[tid + (4 * k + 0) * 1024];
        float4 c = p4[tid + (4 * k + 1) * 1024];
        float4 d = p4[tid + (4 * k + 2) * 1024];
        float4 e = p4[tid + (4 * k + 3) * 1024];
        s0 += a.x + a.y + a.z + a.w;
        q0 += a.x * a.x + a.y * a.y + a.z * a.z + a.w * a.w;
        s1 += c.x + c.y + c.z + c.w;
        q1 += c.x * c.x + c.y * c.y + c.z * c.z + c.w * c.w;
        s2 += d.x + d.y + d.z + d.w;
        q2 += d.x * d.x + d.y * d.y + d.z * d.z + d.w * d.w;
        s3 += e.x + e.y + e.z + e.w;
        q3 += e.x * e.x + e.y * e.y + e.z * e.z + e.w * e.w;
    }
    float s = (s0 + s1) + (s2 + s3);
    float q = (q0 + q1) + (q2 + q3);

    __shared__ float rs[32], rq[32], stat[2];
    __shared__ float sSc[CPG], sSh[CPG];
    #pragma unroll
    for (int off = 16; off > 0; off >>= 1) {
        s += __shfl_xor_sync(0xffffffffu, s, off);
        q += __shfl_xor_sync(0xffffffffu, q, off);
    }
    if ((tid & 31) == 0) { rs[tid >> 5] = s; rq[tid >> 5] = q; }
    __syncthreads();
    if (tid < 32) {
        float ws = rs[tid], wq = rq[tid];
        #pragma unroll
        for (int off = 16; off > 0; off >>= 1) {
            ws += __shfl_xor_sync(0xffffffffu, ws, off);
            wq += __shfl_xor_sync(0xffffffffu, wq, off);
        }
        if (tid == 0) {
            const float inv_n = 1.f / (float)(CPG * HWSZ);
            float mean = ws * inv_n;
            float var  = wq * inv_n - mean * mean;
            stat[0] = mean;
            stat[1] = rsqrtf(var + 1e-5f);
        }
    }
    __syncthreads();
    if (tid < CPG) {
        const float QSC = 0.125f * 1.4426950408889634f;
        float mean = stat[0], rstd = stat[1];
        int c = g * CPG + tid;
        float sc = rstd * w[c];
        float sh = bs[c] - mean * sc;
        if (g % 3 == 1) { sc *= QSC; sh *= QSC; }    // whole group is Q
        sSc[tid] = sc;
        sSh[tid] = sh;
    }
    __syncthreads();

    __half* oh = g_xh + base;
    #pragma unroll
    for (int k = 0; k < 8; k++) {
        int chunk = tid + k * 1024;
        int e = chunk * 8;
        int c = e >> 10;
        float sc = sSc[c], sh = sSh[c];
        float4 v0 = p4[chunk * 2];
        float4 v1 = p4[chunk * 2 + 1];
        uint4 pk;
        pk.x = packh2(v0.x * sc + sh, v0.y * sc + sh);
        pk.y = packh2(v0.z * sc + sh, v0.w * sc + sh);
        pk.z = packh2(v1.x * sc + sh, v1.y * sc + sh);
        pk.w = packh2(v1.z * sc + sh, v1.w * sc + sh);
        *(uint4*)&oh[e] = pk;
    }
}

// ---------------------------------------------------------------------------
// helpers
// ---------------------------------------------------------------------------
__device__ __forceinline__ uint32_t smem_u32(const void* p) {
    uint32_t a;
    asm("{ .reg .u64 t; cvta.to.shared.u64 t, %1; cvt.u32.u64 %0, t; }"
        : "=r"(a) : "l"(p));
    return a;
}
__device__ __forceinline__ void ldsm4(uint32_t* r, uint32_t addr) {
    asm volatile("ldmatrix.sync.aligned.m8n8.x4.shared.b16 {%0,%1,%2,%3}, [%4];"
                 : "=r"(r[0]), "=r"(r[1]), "=r"(r[2]), "=r"(r[3]) : "r"(addr));
}
__device__ __forceinline__ void ldsm4t(uint32_t* r, uint32_t addr) {
    asm volatile("ldmatrix.sync.aligned.m8n8.x4.trans.shared.b16 {%0,%1,%2,%3}, [%4];"
                 : "=r"(r[0]), "=r"(r[1]), "=r"(r[2]), "=r"(r[3]) : "r"(addr));
}
// f32-accumulator HMMA (PV — output precision matters)
__device__ __forceinline__ void mma16816(float* d, const uint32_t* a,
                                         uint32_t b0, uint32_t b1) {
    asm volatile(
        "mma.sync.aligned.m16n8k16.row.col.f32.f16.f16.f32 "
        "{%0,%1,%2,%3}, {%4,%5,%6,%7}, {%8,%9}, {%0,%1,%2,%3};"
        : "+f"(d[0]), "+f"(d[1]), "+f"(d[2]), "+f"(d[3])
        : "r"(a[0]), "r"(a[1]), "r"(a[2]), "r"(a[3]), "r"(b0), "r"(b1));
}
// f16-accumulator HMMA (2x rate) — S GEMM
__device__ __forceinline__ void mma16816h(uint32_t* d, const uint32_t* a,
                                          uint32_t b0, uint32_t b1) {
    asm volatile(
        "mma.sync.aligned.m16n8k16.row.col.f16.f16.f16.f16 "
        "{%0,%1}, {%2,%3,%4,%5}, {%6,%7}, {%0,%1};"
        : "+r"(d[0]), "+r"(d[1])
        : "r"(a[0]), "r"(a[1]), "r"(a[2]), "r"(a[3]), "r"(b0), "r"(b1));
}
// ex2 on packed half2
__device__ __forceinline__ uint32_t ex2h2(uint32_t x) {
    uint32_t r;
    asm("ex2.approx.f16x2 %0, %1;" : "=r"(r) : "r"(x));
    return r;
}
__device__ __forceinline__ void cp16(uint32_t dst, const void* src) {
    asm volatile("cp.async.cg.shared.global [%0], [%1], 16;"
                 :: "r"(dst), "l"(src) : "memory");
}
__device__ __forceinline__ void cp_commit() {
    asm volatile("cp.async.commit_group;" ::: "memory");
}
template<int N> __device__ __forceinline__ void cp_wait() {
    asm volatile("cp.async.wait_group %0;" :: "n"(N) : "memory");
}
// bulk copy global->smem, completion via mbarrier tx-bytes (base sm_90 PTX)
__device__ __forceinline__ void cpbulk(uint32_t dst, const void* src,
                                       uint32_t bytes, uint32_t mbar) {
    asm volatile(
        "cp.async.bulk.shared::cluster.global.mbarrier::complete_tx::bytes "
        "[%0], [%1], %2, [%3];"
        :: "r"(dst), "l"(src), "r"(bytes), "r"(mbar) : "memory");
}
__device__ __forceinline__ void mb_init(uint32_t a, uint32_t c) {
    asm volatile("mbarrier.init.shared.b64 [%0], %1;" :: "r"(a), "r"(c) : "memory");
}
__device__ __forceinline__ void mb_expect(uint32_t a, uint32_t tx) {
    asm volatile("mbarrier.arrive.expect_tx.shared.b64 _, [%0], %1;"
                 :: "r"(a), "r"(tx) : "memory");
}
__device__ __forceinline__ void mb_wait(uint32_t a, uint32_t ph) {
    uint32_t done;
    asm volatile("{\n\t.reg .pred p;\n\t"
                 "mbarrier.try_wait.parity.acquire.cta.shared::cta.b64 p, [%1], %2;\n\t"
                 "selp.b32 %0, 1, 0, p;\n\t}"
                 : "=r"(done) : "r"(a), "r"(ph) : "memory");
    if (!done) {
        asm volatile("{\n\t.reg .pred P1;\n\t"
                     "WAIT_LOOP_%=:\n\t"
                     "mbarrier.try_wait.parity.acquire.cta.shared::cta.b64 P1, [%0], %1, 0x989680;\n\t"
                     "@P1 bra.uni WAIT_DONE_%=;\n\t"
                     "bra.uni WAIT_LOOP_%=;\n\t"
                     "WAIT_DONE_%=:\n\t}"
                     :: "r"(a), "r"(ph) : "memory");
    }
}

// SMEM layout (bytes, dynamic):
//   Qs  half[64][136]          @ 0         (17408)
//   3 x { Ks half[64][72] ; Vs half[64][72] }  @ 17408, stride 18432
// Osm float[64][132] (33792B) overlays @0 in the epilogue.
// Total 72704 B -> 3 CTAs/SM.
#define QS_OFF   0
#define BUF_OFF  17408
#define BUF_STR  18432
#define SMEM_SZ  72704
#define TILE_TX  16384u     // 2*64 rows * 128B per K/V tile

// ---------------------------------------------------------------------------
// Kernel B: HMMA flash attention. K/V staged by cp.async.bulk (warp 0 issues
// 4 warp-instructions per tile) + mbarrier completion — kills the LDGSTS
// instruction flood so occupancy 3 actually buys latency cover.
// Compute: f16-acc S, f32-acc PV, chunk pipeline S(p);PV(p-1);exp(p).
// grid = (8 q-tiles of 128, 64 bh), 256 threads, occupancy 3.
// ---------------------------------------------------------------------------
__global__ __launch_bounds__(256, 3)
void attn_mma(float* __restrict__ out) {
    extern __shared__ char smc[];
    __shared__ __align__(8) unsigned long long mbars[3];
    float* Osm = (float*)smc;

    const uint32_t sb = smem_u32(smc);
    const uint32_t mb0 = smem_u32(&mbars[0]);
    const int tid = threadIdx.x;
    const int wid = tid >> 5, lane = tid & 31;
    const int qbase = wid * 16;
    const int bh = blockIdx.y;
    const int q0 = blockIdx.x * 128;
    const __half* xh = g_xh + ((size_t)(bh >> 3) * NC + (size_t)(bh & 7) * 192) * HWSZ;

    if (tid == 0) {
        mb_init(mb0, 1);
        mb_init(mb0 + 8, 1);
        mb_init(mb0 + 16, 1);
    }
    // Q prologue: 64 rows x 256B = 1024 chunks of 16B, 4 per thread.
    #pragma unroll
    for (int k = 0; k < 4; k++) {
        int idx = tid + k * 256;
        int row = idx >> 4, ch = idx & 15;
        cp16(sb + QS_OFF + (uint32_t)(row * 272 + ch * 16),
             xh + (size_t)(64 + row) * HWSZ + q0 + ch * 8);
    }
    cp_commit();
    __syncthreads();       // mbarrier init visible to all

    // Stage K/V tiles 0 and 1 via bulk copies (warp 0; 32 lanes x 4 rows).
    if (wid == 0) {
        #pragma unroll
        for (int t0 = 0; t0 < 2; t0++) {
            uint32_t mb = mb0 + t0 * 8;
            uint32_t bufb = sb + BUF_OFF + t0 * BUF_STR;
            if (lane == 0) mb_expect(mb, TILE_TX);
            __syncwarp();
            #pragma unroll
            for (int it = 0; it < 2; it++) {
                int row = lane + it * 32;
                cpbulk(bufb + (uint32_t)(row * 144),
                       xh + (size_t)row * HWSZ + t0 * 64, 128u, mb);
                cpbulk(bufb + 9216 + (uint32_t)(row * 144),
                       xh + (size_t)(128 + row) * HWSZ + t0 * 64, 128u, mb);
            }
        }
    }

    cp_wait<0>();          // Q landed
    __syncthreads();

    // ---- Preload Q fragments (persist across all k-tiles) ----
    uint32_t qf[4][4];
    {
        int crow0 = ((lane & 16) >> 1) + (lane & 7);
        int qcol  = qbase + (lane & 8);
        #pragma unroll
        for (int kc = 0; kc < 4; kc++)
            ldsm4t(qf[kc], sb + QS_OFF + (uint32_t)((kc * 16 + crow0) * 136 + qcol) * 2);
    }

    float o[8][4];
    #pragma unroll
    for (int i = 0; i < 8; i++)
        #pragma unroll
        for (int j = 0; j < 4; j++) o[i][j] = 0.f;
    float l0 = 0.f, l1 = 0.f;

    const uint32_t kfo = (uint32_t)(((lane & 8) + (lane & 7)) * 72 + ((lane & 16) >> 1)) * 2;
    const uint32_t vfo = (uint32_t)((((lane & 16) >> 1) + (lane & 7)) * 72 + (lane & 8)) * 2 + 9216;

    for (int kt = 0; kt < 16; kt++) {
        // Tile kt ready?  (stage kt%3, use kt/3 -> parity (kt/3)&1)
        mb_wait(mb0 + (kt % 3) * 8, (uint32_t)((kt / 3) & 1));
        __syncthreads();   // all warps done reading tile kt-1's buffer

        // Prefetch tile kt+2 into buffer (kt+2)%3 (now free).
        if (kt + 2 < 16 && wid == 0) {
            const int jn = (kt + 2) * 64;
            uint32_t mb = mb0 + ((kt + 2) % 3) * 8;
            uint32_t bufb = sb + BUF_OFF + ((kt + 2) % 3) * BUF_STR;
            if (lane == 0) mb_expect(mb, TILE_TX);
            __syncwarp();
            #pragma unroll
            for (int it = 0; it < 2; it++) {
                int row = lane + it * 32;
                cpbulk(bufb + (uint32_t)(row * 144),
                       xh + (size_t)row * HWSZ + jn, 128u, mb);
                cpbulk(bufb + 9216 + (uint32_t)(row * 144),
                       xh + (size_t)(128 + row) * HWSZ + jn, 128u, mb);
            }
        }

        const uint32_t bufb = sb + BUF_OFF + (kt % 3) * BUF_STR;
        const uint32_t kfb = bufb + kfo;
        const uint32_t vfb = bufb + vfo;

        // ---- chunk-pipelined S / exp / PV ----
        uint32_t pprev[4];          // packed P for chunk p-1
        #pragma unroll
        for (int p = 0; p < 4; p++) {
            // S-MMAs for n-chunk p (16 keys) — fp16 accumulators
            uint32_t s0h[2] = {0u, 0u};
            uint32_t s1h[2] = {0u, 0u};
            #pragma unroll
            for (int kc = 0; kc < 4; kc++) {
                uint32_t kb[4];
                ldsm4t(kb, kfb + (uint32_t)(kc * 16 * 72 + p * 16) * 2);
                mma16816h(s0h, qf[kc], kb[0], kb[1]);
                mma16816h(s1h, qf[kc], kb[2], kb[3]);
            }
            // PV-MMAs for chunk p-1
            if (p > 0) {
                const int jc = p - 1;
                #pragma unroll
                for (int vp = 0; vp < 4; vp++) {
                    uint32_t vb[4];
                    ldsm4(vb, vfb + (uint32_t)(vp * 16 * 72 + jc * 16) * 2);
                    mma16816(o[2 * vp],     pprev, vb[0], vb[1]);
                    mma16816(o[2 * vp + 1], pprev, vb[2], vb[3]);
                }
            }
            // exp chunk p (fragments already half2-packed)
            pprev[0] = ex2h2(s0h[0]);
            pprev[1] = ex2h2(s0h[1]);
            pprev[2] = ex2h2(s1h[0]);
            pprev[3] = ex2h2(s1h[1]);
            __half2 u0 = __hadd2(*(__half2*)&pprev[0], *(__half2*)&pprev[2]);
            __half2 u1 = __hadd2(*(__half2*)&pprev[1], *(__half2*)&pprev[3]);
            l0 += __low2float(u0) + __high2float(u0);
            l1 += __low2float(u1) + __high2float(u1);
        }
        // tail: PV for chunk 3
        #pragma unroll
        for (int vp = 0; vp < 4; vp++) {
            uint32_t vb[4];
            ldsm4(vb, vfb + (uint32_t)(vp * 16 * 72 + 3 * 16) * 2);
            mma16816(o[2 * vp],     pprev, vb[0], vb[1]);
            mma16816(o[2 * vp + 1], pprev, vb[2], vb[3]);
        }
    }

    // ---- Epilogue: normalize, stage via SMEM, coalesced store ----
    l0 += __shfl_xor_sync(0xffffffffu, l0, 1);
    l0 += __shfl_xor_sync(0xffffffffu, l0, 2);
    l1 += __shfl_xor_sync(0xffffffffu, l1, 1);
    l1 += __shfl_xor_sync(0xffffffffu, l1, 2);
    float inv0 = 1.f / l0, inv1 = 1.f / l1;

    __syncthreads();       // all warps done with Q/K/V SMEM
    {
        int qa = qbase + (lane >> 2);
        #pragma unroll
        for (int vn = 0; vn < 8; vn++) {
            int vd = vn * 8 + (lane & 3) * 2;
            Osm[vd * 132 + qa]           = o[vn][0] * inv0;
            Osm[(vd + 1) * 132 + qa]     = o[vn][1] * inv0;
            Osm[vd * 132 + qa + 8]       = o[vn][2] * inv1;
            Osm[(vd + 1) * 132 + qa + 8] = o[vn][3] * inv1;
        }
    }
    __syncthreads();

    float* gout = out + ((size_t)(bh * 64)) * HWSZ + q0;
    #pragma unroll
    for (int k = 0; k < 8; k++) {
        int idx = tid + k * 256;
        int vd = idx >> 5, fq = (idx & 31) * 4;
        *(float4*)(gout + (size_t)vd * HWSZ + fq) = *(const float4*)&Osm[vd * 132 + fq];
    }
}

// ---------------------------------------------------------------------------
extern "C" void kernel_launch(void* const* d_in, const int* in_sizes, int n_in,
                              void* d_out, int out_size) {
    const float* x    = (const float*)d_in[0];
    const float* w    = (const float*)d_in[1];
    const float* bias = (const float*)d_in[2];
    float* out = (float*)d_out;

    cudaFuncSetAttribute(attn_mma, cudaFuncAttributeMaxDynamicSharedMemorySize, SMEM_SZ);

    gn_fused_kernel<<<NB * NG, 1024>>>(x, w, bias);
    attn_mma<<<dim3(8, 64), 256, SMEM_SZ>>>(out);
}

// round 17
// speedup vs baseline: 2.3376x; 2.3376x over previous
#include <cuda_runtime.h>
#include <cuda_fp16.h>
#include <cstdint>
#include <math.h>

#define NB   8
#define NC   1536
#define HWSZ 1024
#define NG   24
#define CPG  64

__device__ __half g_xh[(size_t)NB * NC * HWSZ];   // GN-normalized fp16 tensor

// pack two floats into half2 {lo=a, hi=b}
__device__ __forceinline__ uint32_t packh2(float a, float b) {
    uint32_t r;
    asm("cvt.rn.f16x2.f32 %0, %1, %2;" : "=r"(r) : "f"(b), "f"(a));
    return r;
}

// ---------------------------------------------------------------------------
// Kernel A (fused): per-(b,group) stats + fp16 conversion in one pass.
// ---------------------------------------------------------------------------
__global__ __launch_bounds__(1024)
void gn_fused_kernel(const float* __restrict__ x,
                     const float* __restrict__ w,
                     const float* __restrict__ bs) {
    const int b = blockIdx.x / NG;
    const int g = blockIdx.x % NG;
    const int tid = threadIdx.x;
    const size_t base = ((size_t)b * NC + (size_t)g * CPG) * HWSZ;
    const float4* p4 = (const float4*)(x + base);

    float s0 = 0.f, s1 = 0.f, s2 = 0.f, s3 = 0.f;
    float q0 = 0.f, q1 = 0.f, q2 = 0.f, q3 = 0.f;
    #pragma unroll
    for (int k = 0; k < 4; k++) {
        float4 a = p4[tid + (4 * k + 0) * 1024];
        float4 c = p4[tid + (4 * k + 1) * 1024];
        float4 d = p4[tid + (4 * k + 2) * 1024];
        float4 e = p4[tid + (4 * k + 3) * 1024];
        s0 += a.x + a.y + a.z + a.w;
        q0 += a.x * a.x + a.y * a.y + a.z * a.z + a.w * a.w;
        s1 += c.x + c.y + c.z + c.w;
        q1 += c.x * c.x + c.y * c.y + c.z * c.z + c.w * c.w;
        s2 += d.x + d.y + d.z + d.w;
        q2 += d.x * d.x + d.y * d.y + d.z * d.z + d.w * d.w;
        s3 += e.x + e.y + e.z + e.w;
        q3 += e.x * e.x + e.y * e.y + e.z * e.z + e.w * e.w;
    }
    float s = (s0 + s1) + (s2 + s3);
    float q = (q0 + q1) + (q2 + q3);

    __shared__ float rs[32], rq[32], stat[2];
    __shared__ float sSc[CPG], sSh[CPG];
    #pragma unroll
    for (int off = 16; off > 0; off >>= 1) {
        s += __shfl_xor_sync(0xffffffffu, s, off);
        q += __shfl_xor_sync(0xffffffffu, q, off);
    }
    if ((tid & 31) == 0) { rs[tid >> 5] = s; rq[tid >> 5] = q; }
    __syncthreads();
    if (tid < 32) {
        float ws = rs[tid], wq = rq[tid];
        #pragma unroll
        for (int off = 16; off > 0; off >>= 1) {
            ws += __shfl_xor_sync(0xffffffffu, ws, off);
            wq += __shfl_xor_sync(0xffffffffu, wq, off);
        }
        if (tid == 0) {
            const float inv_n = 1.f / (float)(CPG * HWSZ);
            float mean = ws * inv_n;
            float var  = wq * inv_n - mean * mean;
            stat[0] = mean;
            stat[1] = rsqrtf(var + 1e-5f);
        }
    }
    __syncthreads();
    if (tid < CPG) {
        const float QSC = 0.125f * 1.4426950408889634f;
        float mean = stat[0], rstd = stat[1];
        int c = g * CPG + tid;
        float sc = rstd * w[c];
        float sh = bs[c] - mean * sc;
        if (g % 3 == 1) { sc *= QSC; sh *= QSC; }    // whole group is Q
        sSc[tid] = sc;
        sSh[tid] = sh;
    }
    __syncthreads();

    __half* oh = g_xh + base;
    #pragma unroll
    for (int k = 0; k < 8; k++) {
        int chunk = tid + k * 1024;
        int e = chunk * 8;
        int c = e >> 10;
        float sc = sSc[c], sh = sSh[c];
        float4 v0 = p4[chunk * 2];
        float4 v1 = p4[chunk * 2 + 1];
        uint4 pk;
        pk.x = packh2(v0.x * sc + sh, v0.y * sc + sh);
        pk.y = packh2(v0.z * sc + sh, v0.w * sc + sh);
        pk.z = packh2(v1.x * sc + sh, v1.y * sc + sh);
        pk.w = packh2(v1.z * sc + sh, v1.w * sc + sh);
        *(uint4*)&oh[e] = pk;
    }
}

// ---------------------------------------------------------------------------
// helpers
// ---------------------------------------------------------------------------
__device__ __forceinline__ uint32_t smem_u32(const void* p) {
    uint32_t a;
    asm("{ .reg .u64 t; cvta.to.shared.u64 t, %1; cvt.u32.u64 %0, t; }"
        : "=r"(a) : "l"(p));
    return a;
}
__device__ __forceinline__ void ldsm4(uint32_t* r, uint32_t addr) {
    asm volatile("ldmatrix.sync.aligned.m8n8.x4.shared.b16 {%0,%1,%2,%3}, [%4];"
                 : "=r"(r[0]), "=r"(r[1]), "=r"(r[2]), "=r"(r[3]) : "r"(addr));
}
__device__ __forceinline__ void ldsm4t(uint32_t* r, uint32_t addr) {
    asm volatile("ldmatrix.sync.aligned.m8n8.x4.trans.shared.b16 {%0,%1,%2,%3}, [%4];"
                 : "=r"(r[0]), "=r"(r[1]), "=r"(r[2]), "=r"(r[3]) : "r"(addr));
}
// f32-accumulator HMMA (PV — output precision matters)
__device__ __forceinline__ void mma16816(float* d, const uint32_t* a,
                                         uint32_t b0, uint32_t b1) {
    asm volatile(
        "mma.sync.aligned.m16n8k16.row.col.f32.f16.f16.f32 "
        "{%0,%1,%2,%3}, {%4,%5,%6,%7}, {%8,%9}, {%0,%1,%2,%3};"
        : "+f"(d[0]), "+f"(d[1]), "+f"(d[2]), "+f"(d[3])
        : "r"(a[0]), "r"(a[1]), "r"(a[2]), "r"(a[3]), "r"(b0), "r"(b1));
}
// f16-accumulator HMMA — S GEMM
__device__ __forceinline__ void mma16816h(uint32_t* d, const uint32_t* a,
                                          uint32_t b0, uint32_t b1) {
    asm volatile(
        "mma.sync.aligned.m16n8k16.row.col.f16.f16.f16.f16 "
        "{%0,%1}, {%2,%3,%4,%5}, {%6,%7}, {%0,%1};"
        : "+r"(d[0]), "+r"(d[1])
        : "r"(a[0]), "r"(a[1]), "r"(a[2]), "r"(a[3]), "r"(b0), "r"(b1));
}
// ex2 on packed half2
__device__ __forceinline__ uint32_t ex2h2(uint32_t x) {
    uint32_t r;
    asm("ex2.approx.f16x2 %0, %1;" : "=r"(r) : "r"(x));
    return r;
}
__device__ __forceinline__ void cp16(uint32_t dst, const void* src) {
    asm volatile("cp.async.cg.shared.global [%0], [%1], 16;"
                 :: "r"(dst), "l"(src) : "memory");
}
// this thread's prior cp.asyncs arrive (noinc) on mbarrier when complete
__device__ __forceinline__ void cp_mb_arrive(uint32_t mbar) {
    asm volatile("cp.async.mbarrier.arrive.noinc.shared.b64 [%0];"
                 :: "r"(mbar) : "memory");
}
__device__ __forceinline__ void mb_init(uint32_t a, uint32_t c) {
    asm volatile("mbarrier.init.shared.b64 [%0], %1;" :: "r"(a), "r"(c) : "memory");
}
__device__ __forceinline__ void mb_arrive(uint32_t a) {
    asm volatile("mbarrier.arrive.shared.b64 _, [%0];" :: "r"(a) : "memory");
}
__device__ __forceinline__ void mb_wait(uint32_t a, uint32_t ph) {
    uint32_t done;
    asm volatile("{\n\t.reg .pred p;\n\t"
                 "mbarrier.try_wait.parity.acquire.cta.shared::cta.b64 p, [%1], %2;\n\t"
                 "selp.b32 %0, 1, 0, p;\n\t}"
                 : "=r"(done) : "r"(a), "r"(ph) : "memory");
    if (!done) {
        asm volatile("{\n\t.reg .pred P1;\n\t"
                     "WAIT_LOOP_%=:\n\t"
                     "mbarrier.try_wait.parity.acquire.cta.shared::cta.b64 P1, [%0], %1, 0x989680;\n\t"
                     "@P1 bra.uni WAIT_DONE_%=;\n\t"
                     "bra.uni WAIT_LOOP_%=;\n\t"
                     "WAIT_DONE_%=:\n\t}"
                     :: "r"(a), "r"(ph) : "memory");
    }
}

// SMEM layout (bytes, dynamic):
//   Qs  half[64][136]          @ 0         (17408)
//   4 x { Ks half[64][72] ; Vs half[64][72] }  @ 17408, stride 18432
// Osm float[64][132] (33792B) overlays @0 in the epilogue (guarded by a
// full __syncthreads after the mainloop).
#define QS_OFF   0
#define BUF_OFF  17408
#define BUF_STR  18432
#define SMEM_SZ  91136

// ---------------------------------------------------------------------------
// Kernel B: HMMA flash attention with FREE-RUNNING WARPS: no per-tile
// __syncthreads. Tile readiness via cp.async.mbarrier.arrive (count 256);
// buffer-reuse safety via per-warp done-mbarriers (count 8). 4 buffers give
// warps ~2 tiles of legal skew so pipes overlap across warps.
// Compute identical to R15: f16-acc S, f32-acc PV, chunk pipeline.
// grid = (8 q-tiles of 128, 64 bh), 256 threads, occupancy 2.
// ---------------------------------------------------------------------------
__global__ __launch_bounds__(256, 2)
void attn_mma(float* __restrict__ out) {
    extern __shared__ char smc[];
    __shared__ __align__(8) unsigned long long mbR_s[4], mbD_s[4];
    float* Osm = (float*)smc;

    const uint32_t sb  = smem_u32(smc);
    const uint32_t mbR = smem_u32(&mbR_s[0]);
    const uint32_t mbD = smem_u32(&mbD_s[0]);
    const int tid = threadIdx.x;
    const int wid = tid >> 5, lane = tid & 31;
    const int qbase = wid * 16;
    const int bh = blockIdx.y;
    const int q0 = blockIdx.x * 128;
    const __half* xh = g_xh + ((size_t)(bh >> 3) * NC + (size_t)(bh & 7) * 192) * HWSZ;

    if (tid == 0) {
        #pragma unroll
        for (int i = 0; i < 4; i++) {
            mb_init(mbR + i * 8, 256);   // ready: one arrive per thread (cp.async)
            mb_init(mbD + i * 8, 8);     // done:  one arrive per warp
        }
    }
    __syncthreads();       // init visible before any arrive

    // Q prologue: 64 rows x 256B = 1024 chunks of 16B, 4 per thread.
    #pragma unroll
    for (int k = 0; k < 4; k++) {
        int idx = tid + k * 256;
        int row = idx >> 4, ch = idx & 15;
        cp16(sb + QS_OFF + (uint32_t)(row * 272 + ch * 16),
             xh + (size_t)(64 + row) * HWSZ + q0 + ch * 8);
    }
    // Stage tiles 0 and 1 (Q copies fold into tile-0's ready arrive).
    #pragma unroll
    for (int t0 = 0; t0 < 2; t0++) {
        uint32_t bufb = sb + BUF_OFF + t0 * BUF_STR;
        #pragma unroll
        for (int k = 0; k < 2; k++) {
            int idx = tid + k * 256;
            int row = idx >> 3, ch = idx & 7;
            cp16(bufb + (uint32_t)(row * 144 + ch * 16),
                 xh + (size_t)row * HWSZ + t0 * 64 + ch * 8);
        }
        #pragma unroll
        for (int k = 0; k < 2; k++) {
            int idx = tid + k * 256;
            int row = idx >> 3, ch = idx & 7;
            cp16(bufb + 9216 + (uint32_t)(row * 144 + ch * 16),
                 xh + (size_t)(128 + row) * HWSZ + t0 * 64 + ch * 8);
        }
        cp_mb_arrive(mbR + t0 * 8);
    }

    // Wait tile 0 ready (covers Q), then preload Q fragments.
    mb_wait(mbR + 0, 0u);
    uint32_t qf[4][4];
    {
        int crow0 = ((lane & 16) >> 1) + (lane & 7);
        int qcol  = qbase + (lane & 8);
        #pragma unroll
        for (int kc = 0; kc < 4; kc++)
            ldsm4t(qf[kc], sb + QS_OFF + (uint32_t)((kc * 16 + crow0) * 136 + qcol) * 2);
    }

    float o[8][4];
    #pragma unroll
    for (int i = 0; i < 8; i++)
        #pragma unroll
        for (int j = 0; j < 4; j++) o[i][j] = 0.f;
    float l0 = 0.f, l1 = 0.f;

    const uint32_t kfo = (uint32_t)(((lane & 8) + (lane & 7)) * 72 + ((lane & 16) >> 1)) * 2;
    const uint32_t vfo = (uint32_t)((((lane & 16) >> 1) + (lane & 7)) * 72 + (lane & 8)) * 2 + 9216;

    for (int kt = 0; kt < 16; kt++) {
        // Tile kt ready?  barrier kt&3, completed-phase parity (kt>>2)&1.
        mb_wait(mbR + (kt & 3) * 8, (uint32_t)((kt >> 2) & 1));

        // Stage tile kt+2 into buffer (kt+2)&3 — previous occupant is tile
        // kt-2; wait until all warps are done reading it (skip for kt<2:
        // buffers 2,3 are fresh).
        if (kt + 2 < 16) {
            if (kt >= 2)
                mb_wait(mbD + ((kt + 2) & 3) * 8, (uint32_t)(((kt - 2) >> 2) & 1));
            const int jn = (kt + 2) * 64;
            uint32_t bufb = sb + BUF_OFF + ((kt + 2) & 3) * BUF_STR;
            #pragma unroll
            for (int k = 0; k < 2; k++) {
                int idx = tid + k * 256;
                int row = idx >> 3, ch = idx & 7;
                cp16(bufb + (uint32_t)(row * 144 + ch * 16),
                     xh + (size_t)row * HWSZ + jn + ch * 8);
            }
            #pragma unroll
            for (int k = 0; k < 2; k++) {
                int idx = tid + k * 256;
                int row = idx >> 3, ch = idx & 7;
                cp16(bufb + 9216 + (uint32_t)(row * 144 + ch * 16),
                     xh + (size_t)(128 + row) * HWSZ + jn + ch * 8);
            }
            cp_mb_arrive(mbR + ((kt + 2) & 3) * 8);
        }

        const uint32_t bufb = sb + BUF_OFF + (kt & 3) * BUF_STR;
        const uint32_t kfb = bufb + kfo;
        const uint32_t vfb = bufb + vfo;

        // ---- chunk-pipelined S / exp / PV ----
        uint32_t pprev[4];          // packed P for chunk p-1
        #pragma unroll
        for (int p = 0; p < 4; p++) {
            // S-MMAs for n-chunk p (16 keys) — fp16 accumulators
            uint32_t s0h[2] = {0u, 0u};
            uint32_t s1h[2] = {0u, 0u};
            #pragma unroll
            for (int kc = 0; kc < 4; kc++) {
                uint32_t kb[4];
                ldsm4t(kb, kfb + (uint32_t)(kc * 16 * 72 + p * 16) * 2);
                mma16816h(s0h, qf[kc], kb[0], kb[1]);
                mma16816h(s1h, qf[kc], kb[2], kb[3]);
            }
            // PV-MMAs for chunk p-1
            if (p > 0) {
                const int jc = p - 1;
                #pragma unroll
                for (int vp = 0; vp < 4; vp++) {
                    uint32_t vb[4];
                    ldsm4(vb, vfb + (uint32_t)(vp * 16 * 72 + jc * 16) * 2);
                    mma16816(o[2 * vp],     pprev, vb[0], vb[1]);
                    mma16816(o[2 * vp + 1], pprev, vb[2], vb[3]);
                }
            }
            // exp chunk p (fragments already half2-packed)
            pprev[0] = ex2h2(s0h[0]);
            pprev[1] = ex2h2(s0h[1]);
            pprev[2] = ex2h2(s1h[0]);
            pprev[3] = ex2h2(s1h[1]);
            __half2 u0 = __hadd2(*(__half2*)&pprev[0], *(__half2*)&pprev[2]);
            __half2 u1 = __hadd2(*(__half2*)&pprev[1], *(__half2*)&pprev[3]);
            l0 += __low2float(u0) + __high2float(u0);
            l1 += __low2float(u1) + __high2float(u1);
        }
        // tail: PV for chunk 3
        #pragma unroll
        for (int vp = 0; vp < 4; vp++) {
            uint32_t vb[4];
            ldsm4(vb, vfb + (uint32_t)(vp * 16 * 72 + 3 * 16) * 2);
            mma16816(o[2 * vp],     pprev, vb[0], vb[1]);
            mma16816(o[2 * vp + 1], pprev, vb[2], vb[3]);
        }

        // This warp is done reading tile kt's buffer.
        __syncwarp();
        if (lane == 0) mb_arrive(mbD + (kt & 3) * 8);
    }

    // ---- Epilogue: normalize, stage via SMEM, coalesced store ----
    l0 += __shfl_xor_sync(0xffffffffu, l0, 1);
    l0 += __shfl_xor_sync(0xffffffffu, l0, 2);
    l1 += __shfl_xor_sync(0xffffffffu, l1, 1);
    l1 += __shfl_xor_sync(0xffffffffu, l1, 2);
    float inv0 = 1.f / l0, inv1 = 1.f / l1;

    __syncthreads();       // all warps past the mainloop before Osm overlays
    {
        int qa = qbase + (lane >> 2);
        #pragma unroll
        for (int vn = 0; vn < 8; vn++) {
            int vd = vn * 8 + (lane & 3) * 2;
            Osm[vd * 132 + qa]           = o[vn][0] * inv0;
            Osm[(vd + 1) * 132 + qa]     = o[vn][1] * inv0;
            Osm[vd * 132 + qa + 8]       = o[vn][2] * inv1;
            Osm[(vd + 1) * 132 + qa + 8] = o[vn][3] * inv1;
        }
    }
    __syncthreads();

    float* gout = out + ((size_t)(bh * 64)) * HWSZ + q0;
    #pragma unroll
    for (int k = 0; k < 8; k++) {
        int idx = tid + k * 256;
        int vd = idx >> 5, fq = (idx & 31) * 4;
        *(float4*)(gout + (size_t)vd * HWSZ + fq) = *(const float4*)&Osm[vd * 132 + fq];
    }
}

// ---------------------------------------------------------------------------
extern "C" void kernel_launch(void* const* d_in, const int* in_sizes, int n_in,
                              void* d_out, int out_size) {
    const float* x    = (const float*)d_in[0];
    const float* w    = (const float*)d_in[1];
    const float* bias = (const float*)d_in[2];
    float* out = (float*)d_out;

    cudaFuncSetAttribute(attn_mma, cudaFuncAttributeMaxDynamicSharedMemorySize, SMEM_SZ);

    gn_fused_kernel<<<NB * NG, 1024>>>(x, w, bias);
    attn_mma<<<dim3(8, 64), 256, SMEM_SZ>>>(out);
}